// round 13
// baseline (speedup 1.0000x reference)
#include <cuda_runtime.h>
#include <cuda_bf16.h>
#include <cuda_fp16.h>

#define TT 2000
#define NB 64
#define VV 1000
#define ROWS (TT * NB)
#define NEG_BIG (-1e30f)
#define FULLM 0xffffffffu

#define BLK_PER_N 250         // TT / 8 rowreduce blocks per batch element
#define GRID_A (NB * BLK_PER_N)   // 16000
#define EKITER 8              // ceil(TT/256)

// Scratch (no allocation allowed). n-major packed:
//   lo16 = argmax (V=1000 < 65536), hi16 = fp16 bits of maxlp.
// SENTINEL = 0: maxlp <= -log(1+999*exp(-8)) < -0.2 for any normal-ish logits,
// so hi16 bits are never 0 for real data. Zero-init + epilogue reset keep the
// invariant across graph replays (single stream => no cross-replay overlap).
__device__ unsigned g_packed[NB * TT];

__device__ __forceinline__ unsigned poll_ready(const unsigned* p) {
    unsigned x;
    asm volatile("ld.global.cg.u32 %0, [%1];" : "=r"(x) : "l"(p));
    while (x == 0u) {
        __nanosleep(64);
        asm volatile("ld.global.cg.u32 %0, [%1];" : "=r"(x) : "l"(p));
    }
    return x;
}

__global__ __launch_bounds__(256) void ctc_fused_kernel(
    const float* __restrict__ logits, const int* __restrict__ in_lens,
    float* __restrict__ out)
{
    const int bid  = blockIdx.x;
    const int tid  = threadIdx.x;
    const int lane = tid & 31;
    const int wid  = tid >> 5;

    if (bid < GRID_A) {
        // ------------- rowreduce: warp-per-row, n-major block order -------------
        const int n  = bid / BLK_PER_N;
        const int tb = bid - n * BLK_PER_N;
        const int t  = tb * 8 + wid;
        const int row = t * NB + n;

        const float4* __restrict__ p =
            reinterpret_cast<const float4*>(logits + (size_t)row * VV);

        float4 v[8];
#pragma unroll
        for (int j = 0; j < 8; j++) {
            int idx = lane + 32 * j;
            if (idx < 250) v[j] = p[idx];
            else           v[j] = make_float4(NEG_BIG, NEG_BIG, NEG_BIG, NEG_BIG);
        }

        float m = NEG_BIG; int am = 0;
#pragma unroll
        for (int j = 0; j < 8; j++) {
            int base = (lane + 32 * j) * 4;
            float x;
            x = v[j].x; if (x > m) { m = x; am = base;     }
            x = v[j].y; if (x > m) { m = x; am = base + 1; }
            x = v[j].z; if (x > m) { m = x; am = base + 2; }
            x = v[j].w; if (x > m) { m = x; am = base + 3; }
        }
#pragma unroll
        for (int off = 16; off; off >>= 1) {
            float om = __shfl_xor_sync(FULLM, m,  off);
            int   oa = __shfl_xor_sync(FULLM, am, off);
            if (om > m || (om == m && oa < am)) { m = om; am = oa; }
        }

        float s = 0.f;
#pragma unroll
        for (int j = 0; j < 8; j++) {
            s += __expf(v[j].x - m) + __expf(v[j].y - m)
               + __expf(v[j].z - m) + __expf(v[j].w - m);
        }
#pragma unroll
        for (int off = 16; off; off >>= 1)
            s += __shfl_xor_sync(FULLM, s, off);

        if (lane == 0) {
            float maxlp = -__logf(s);                // max - lse (< -0.2 always)
            unsigned hb = (unsigned)__half_as_ushort(__float2half_rn(maxlp));
            g_packed[n * TT + t] = (hb << 16) | (unsigned)am;  // plain STG
        }
        return;                                      // clean exit: no sync/atomic
    }

    // ---------------- epilogue: block-per-n compaction + score ----------------
    __shared__ int   sh_a[256];
    __shared__ float sh_sc[8];

    const int n = bid - GRID_A;
    const int L = in_lens[n];
    unsigned* __restrict__ gp = g_packed + n * TT;

    // Phase 1: poll-load all chunks (per-word data dependence, no fence needed)
    unsigned v[EKITER];
#pragma unroll
    for (int k = 0; k < EKITER; k++) {
        int t = tid + 256 * k;
        v[k] = (t < TT) ? poll_ready(gp + t) : 0u;
    }

    // Phase 2: default paths for ALL t (reference: argmax outside out_len)
#pragma unroll
    for (int k = 0; k < EKITER; k++) {
        int t = tid + 256 * k;
        if (t < TT) out[NB + t * NB + n] = (float)(v[k] & 0xffffu);
    }
    __threadfence_block();
    __syncthreads();      // defaults ordered before compacted-prefix overwrite

    // Phase 3: keep-mask, scan, scatter, score
    float score = 0.f;
    int base  = 0;
    int carry = 0;

#pragma unroll
    for (int k = 0; k < EKITER; k++) {
        int   t = tid + 256 * k;
        int   a = (int)(v[k] & 0xffffu);
        float s = __half2float(__ushort_as_half((unsigned short)(v[k] >> 16)));

        sh_a[tid] = a;
        __syncthreads();

        int  aprev = (tid > 0) ? sh_a[tid - 1] : carry;
        bool valid = (t < TT);
        bool inm   = valid && (t < L);
        bool keep  = inm && (a != 0) && (a != aprev || t == 0);
        if (inm) score += s;

        unsigned bal = __ballot_sync(FULLM, keep);
        carry = sh_a[255];
        __syncthreads();                 // sh_a reads done before count overwrite
        if (lane == 0) sh_a[wid] = __popc(bal);
        __syncthreads();

        int c0 = (lane < 8) ? sh_a[lane] : 0;
        int c  = c0;
#pragma unroll
        for (int off = 1; off < 8; off <<= 1) {
            int y = __shfl_up_sync(FULLM, c, off);
            if (lane >= off) c += y;
        }
        int total  = __shfl_sync(FULLM, c, 7);
        int prefix = base + __shfl_sync(FULLM, c - c0, wid);

        if (keep) {
            int pos = prefix + __popc(bal & ((1u << lane) - 1u));
            out[NB + pos * NB + n] = (float)a;       // compacted prefix
        }
        base += total;
        __syncthreads();                 // counts consumed before next round
    }

#pragma unroll
    for (int off = 16; off; off >>= 1)
        score += __shfl_xor_sync(FULLM, score, off);
    if (lane == 0) sh_sc[wid] = score;
    __syncthreads();

    if (tid == 0) {
        float tot = 0.f;
#pragma unroll
        for (int w = 0; w < 8; w++) tot += sh_sc[w];
        out[n] = tot;                                // score
        out[NB + TT * NB + n] = (float)base;         // out_lens
    }

    // Phase 4: reset sentinel for the next graph replay (loads already done)
#pragma unroll
    for (int k = 0; k < EKITER; k++) {
        int t = tid + 256 * k;
        if (t < TT) gp[t] = 0u;
    }
}

extern "C" void kernel_launch(void* const* d_in, const int* in_sizes, int n_in,
                              void* d_out, int out_size)
{
    const float* logits  = (const float*)d_in[0];
    const int*   in_lens = (const int*)d_in[1];
    float*       out     = (float*)d_out;

    ctc_fused_kernel<<<GRID_A + NB, 256>>>(logits, in_lens, out);
}

// round 14
// speedup vs baseline: 1.0163x; 1.0163x over previous
#include <cuda_runtime.h>
#include <cuda_bf16.h>
#include <cuda_fp16.h>

#define TT 2000
#define NB 64
#define VV 1000
#define ROWS (TT * NB)
#define NEG_BIG (-1e30f)
#define FULLM 0xffffffffu

#define GRID_A 16000          // rowreduce blocks (8 rows each), t-major
#define EKITER 8              // ceil(TT/256)

// Scratch (no allocation allowed). n-major packed:
//   lo16 = argmax (V=1000 < 65536), hi16 = fp16 bits of maxlp.
// SENTINEL = 0: maxlp < 0 strictly, so fp16 hi16 always has the sign bit
// (never 0x0000). Zero-init at load + epilogue reset keep the invariant
// across graph replays (single stream => replays are ordered).
__device__ unsigned g_packed[NB * TT];

__device__ __forceinline__ unsigned poll_ready(const unsigned* p) {
    unsigned x;
    asm volatile("ld.global.cg.u32 %0, [%1];" : "=r"(x) : "l"(p));
    while (x == 0u) {
        __nanosleep(64);
        asm volatile("ld.global.cg.u32 %0, [%1];" : "=r"(x) : "l"(p));
    }
    return x;
}

__global__ __launch_bounds__(256) void ctc_fused_kernel(
    const float* __restrict__ logits, const int* __restrict__ in_lens,
    float* __restrict__ out)
{
    const int bid  = blockIdx.x;
    const int tid  = threadIdx.x;
    const int lane = tid & 31;
    const int wid  = tid >> 5;

    if (bid < GRID_A) {
        // -------- rowreduce: warp-per-row, t-major (contiguous sweep) --------
        const int row = bid * 8 + wid;               // row = t*NB + n
        const float4* __restrict__ p =
            reinterpret_cast<const float4*>(logits + (size_t)row * VV);

        float4 v[8];
#pragma unroll
        for (int j = 0; j < 8; j++) {
            int idx = lane + 32 * j;
            if (idx < 250) v[j] = p[idx];
            else           v[j] = make_float4(NEG_BIG, NEG_BIG, NEG_BIG, NEG_BIG);
        }

        float m = NEG_BIG; int am = 0;
#pragma unroll
        for (int j = 0; j < 8; j++) {
            int base = (lane + 32 * j) * 4;
            float x;
            x = v[j].x; if (x > m) { m = x; am = base;     }
            x = v[j].y; if (x > m) { m = x; am = base + 1; }
            x = v[j].z; if (x > m) { m = x; am = base + 2; }
            x = v[j].w; if (x > m) { m = x; am = base + 3; }
        }
#pragma unroll
        for (int off = 16; off; off >>= 1) {
            float om = __shfl_xor_sync(FULLM, m,  off);
            int   oa = __shfl_xor_sync(FULLM, am, off);
            if (om > m || (om == m && oa < am)) { m = om; am = oa; }
        }

        float s = 0.f;
#pragma unroll
        for (int j = 0; j < 8; j++) {
            s += __expf(v[j].x - m) + __expf(v[j].y - m)
               + __expf(v[j].z - m) + __expf(v[j].w - m);
        }
#pragma unroll
        for (int off = 16; off; off >>= 1)
            s += __shfl_xor_sync(FULLM, s, off);

        if (lane == 0) {
            float maxlp = -__logf(s);                // max - lse (< 0 strictly)
            int t = row >> 6;                        // NB == 64
            int n = row & (NB - 1);
            unsigned hb = (unsigned)__half_as_ushort(__float2half_rn(maxlp));
            g_packed[n * TT + t] = (hb << 16) | (unsigned)am;  // plain STG
        }
        return;                                      // clean exit: no sync/atomic
    }

    // ---------------- epilogue: block-per-n compaction + score ----------------
    __shared__ int   sh_a[256];
    __shared__ float sh_sc[8];

    const int n = bid - GRID_A;
    const int L = in_lens[n];
    unsigned* __restrict__ gp = g_packed + n * TT;

    // Phase 1: poll-load all chunks (per-word data dependence, no fence needed)
    unsigned v[EKITER];
#pragma unroll
    for (int k = 0; k < EKITER; k++) {
        int t = tid + 256 * k;
        v[k] = (t < TT) ? poll_ready(gp + t) : 0u;
    }

    // Phase 2: default paths for ALL t (reference: argmax outside out_len)
#pragma unroll
    for (int k = 0; k < EKITER; k++) {
        int t = tid + 256 * k;
        if (t < TT) out[NB + t * NB + n] = (float)(v[k] & 0xffffu);
    }
    __threadfence_block();
    __syncthreads();      // defaults ordered before compacted-prefix overwrite

    // Phase 3: keep-mask, scan, scatter, score
    float score = 0.f;
    int base  = 0;
    int carry = 0;

#pragma unroll
    for (int k = 0; k < EKITER; k++) {
        int   t = tid + 256 * k;
        int   a = (int)(v[k] & 0xffffu);
        float s = __half2float(__ushort_as_half((unsigned short)(v[k] >> 16)));

        sh_a[tid] = a;
        __syncthreads();

        int  aprev = (tid > 0) ? sh_a[tid - 1] : carry;
        bool valid = (t < TT);
        bool inm   = valid && (t < L);
        bool keep  = inm && (a != 0) && (a != aprev || t == 0);
        if (inm) score += s;

        unsigned bal = __ballot_sync(FULLM, keep);
        carry = sh_a[255];
        __syncthreads();                 // sh_a reads done before count overwrite
        if (lane == 0) sh_a[wid] = __popc(bal);
        __syncthreads();

        int c0 = (lane < 8) ? sh_a[lane] : 0;
        int c  = c0;
#pragma unroll
        for (int off = 1; off < 8; off <<= 1) {
            int y = __shfl_up_sync(FULLM, c, off);
            if (lane >= off) c += y;
        }
        int total  = __shfl_sync(FULLM, c, 7);
        int prefix = base + __shfl_sync(FULLM, c - c0, wid);

        if (keep) {
            int pos = prefix + __popc(bal & ((1u << lane) - 1u));
            out[NB + pos * NB + n] = (float)a;       // compacted prefix
        }
        base += total;
        __syncthreads();                 // counts consumed before next round
    }

#pragma unroll
    for (int off = 16; off; off >>= 1)
        score += __shfl_xor_sync(FULLM, score, off);
    if (lane == 0) sh_sc[wid] = score;
    __syncthreads();

    if (tid == 0) {
        float tot = 0.f;
#pragma unroll
        for (int w = 0; w < 8; w++) tot += sh_sc[w];
        out[n] = tot;                                // score
        out[NB + TT * NB + n] = (float)base;         // out_lens
    }

    // Phase 4: reset sentinel for the next graph replay (loads already done)
#pragma unroll
    for (int k = 0; k < EKITER; k++) {
        int t = tid + 256 * k;
        if (t < TT) gp[t] = 0u;
    }
}

extern "C" void kernel_launch(void* const* d_in, const int* in_sizes, int n_in,
                              void* d_out, int out_size)
{
    const float* logits  = (const float*)d_in[0];
    const int*   in_lens = (const int*)d_in[1];
    float*       out     = (float*)d_out;

    ctc_fused_kernel<<<GRID_A + NB, 256>>>(logits, in_lens, out);
}